// round 16
// baseline (speedup 1.0000x reference)
#include <cuda_runtime.h>
#include <cuda_bf16.h>

// ROI-Align (Mask R-CNN multi-level crop_and_resize), POOL=7, C=256, N=1000.
// R11: R10 structure (single mixed-level param array, 1 prep launch, CPT=4)
// + software-pipelined param loads in k2: next iteration's params are issued
// before the current iteration's 16 gathers, hiding the ~240cyc L2 param
// latency behind gather/store work.

#define NBOX  1000
#define POOLP 49
#define CCH   256
#define MAXS  (NBOX * POOLP)     // 49000
#define CPT   4                  // channels per thread in hot kernel
#define NCG   (CCH / CPT)        // 64 channel groups
#define CHUNKS 16                // k2 grid.y; stride = 256*CHUNKS = 4096
#define STRIDE (256 * CHUNKS)

__device__ int4   g_off[MAXS];   // 4 clamped in-plane offsets
__device__ float4 g_wgt[MAXS];   // 4 bilinear weights (mask folded in)
__device__ int    g_obl[MAXS];   // (level<<28) | (n*12544 + pos)

// -- one-shot prep: per-sample level + bilinear params (no atomics) --------
__global__ __launch_bounds__(256) void kP(const float* __restrict__ boxes) {
    const int s = blockIdx.x * blockDim.x + threadIdx.x;
    if (s >= MAXS) return;

    const int n   = s / POOLP;
    const int pos = s - n * POOLP;
    const int py = pos / 7;
    const int px = pos - py * 7;

    const float y1 = __ldg(boxes + n * 4 + 0);
    const float x1 = __ldg(boxes + n * 4 + 1);
    const float y2 = __ldg(boxes + n * 4 + 2);
    const float x2 = __ldg(boxes + n * 4 + 3);

    // roi_level = clip(round(4 + log2(sqrt(h*w)/0.21875)), 2, 5); round half-to-even.
    const float lvl_f = 4.0f + log2f(sqrtf((y2 - y1) * (x2 - x1)) / 0.21875f);
    int lvl = (int)rintf(lvl_f);
    lvl = lvl < 2 ? 2 : (lvl > 5 ? 5 : lvl);
    const int l = lvl - 2;

    const int H = 256 >> l;
    const int W = H;

    // Match jax f32 arithmetic (t = i / 6.0f as division).
    const float ty = (float)py / 6.0f;
    const float tx = (float)px / 6.0f;
    const float yy = (y1 + (y2 - y1) * ty) * (float)(H - 1);
    const float xx = (x1 + (x2 - x1) * tx) * (float)(W - 1);

    const float y0f = floorf(yy);
    const float x0f = floorf(xx);
    const float wy = yy - y0f;
    const float wx = xx - x0f;

    int iy0 = (int)y0f; iy0 = iy0 < 0 ? 0 : (iy0 > H - 1 ? H - 1 : iy0);
    int iy1 = (iy0 + 1 > H - 1) ? (H - 1) : (iy0 + 1);
    int ix0 = (int)x0f; ix0 = ix0 < 0 ? 0 : (ix0 > W - 1 ? W - 1 : ix0);
    int ix1 = (ix0 + 1 > W - 1) ? (W - 1) : (ix0 + 1);

    const bool inb = (yy >= 0.0f) && (yy <= (float)(H - 1)) &&
                     (xx >= 0.0f) && (xx <= (float)(W - 1));
    const float m = inb ? 1.0f : 0.0f;

    int4 o;
    o.x = iy0 * W + ix0;
    o.y = iy0 * W + ix1;
    o.z = iy1 * W + ix0;
    o.w = iy1 * W + ix1;
    float4 w;
    w.x = m * (1.0f - wy) * (1.0f - wx);
    w.y = m * (1.0f - wy) * wx;
    w.z = m * wy * (1.0f - wx);
    w.w = m * wy * wx;

    g_off[s] = o;
    g_wgt[s] = w;
    g_obl[s] = (l << 28) | (n * (CCH * POOLP) + pos);
}

// -- hot kernel: (channel-group of 4, chunk); params software-pipelined ----
__global__ __launch_bounds__(256) void k2(
    const float* __restrict__ p2,
    const float* __restrict__ p3,
    const float* __restrict__ p4,
    const float* __restrict__ p5,
    float* __restrict__ out)
{
    const int cg    = blockIdx.x;   // 0..NCG-1
    const int chunk = blockIdx.y;   // 0..CHUNKS-1
    const int c0 = cg * CPT;

    int j = chunk * 256 + threadIdx.x;
    if (j >= MAXS) return;

    // Prologue: load first params.
    int4   o   = __ldg(g_off + j);
    float4 w   = __ldg(g_wgt + j);
    int    obl = __ldg(g_obl + j);

    while (true) {
        const int jn = j + STRIDE;

        // Prefetch next iteration's params (overlaps with gathers below).
        int4 on; float4 wn; int obln;
        const bool more = (jn < MAXS);
        if (more) {
            on   = __ldg(g_off + jn);
            wn   = __ldg(g_wgt + jn);
            obln = __ldg(g_obl + jn);
        }

        const int l  = obl >> 28;
        const int ob = obl & 0x0FFFFFFF;
        const int HW = 65536 >> (l + l);

        const float* fm = (l == 0) ? p2 : (l == 1) ? p3 : (l == 2) ? p4 : p5;
        const float* __restrict__ base = fm + (size_t)c0 * HW;

        float v[CPT];
        #pragma unroll
        for (int k = 0; k < CPT; ++k) {
            const float* __restrict__ pl = base + (size_t)k * HW;
            v[k] = w.x * __ldg(pl + o.x) + w.y * __ldg(pl + o.y)
                 + w.z * __ldg(pl + o.z) + w.w * __ldg(pl + o.w);
        }
        #pragma unroll
        for (int k = 0; k < CPT; ++k)
            out[ob + (c0 + k) * POOLP] = v[k];

        if (!more) break;
        o = on; w = wn; obl = obln; j = jn;
    }
}

extern "C" void kernel_launch(void* const* d_in, const int* in_sizes, int n_in,
                              void* d_out, int out_size)
{
    const float* boxes = (const float*)d_in[0];
    const float* p2    = (const float*)d_in[1];
    const float* p3    = (const float*)d_in[2];
    const float* p4    = (const float*)d_in[3];
    const float* p5    = (const float*)d_in[4];
    float* out = (float*)d_out;

    kP<<<(MAXS + 255) / 256, 256>>>(boxes);
    k2<<<dim3(NCG, CHUNKS), 256>>>(p2, p3, p4, p5, out);
}

// round 17
// speedup vs baseline: 1.2017x; 1.2017x over previous
#include <cuda_runtime.h>
#include <cuda_bf16.h>

// ROI-Align (Mask R-CNN multi-level crop_and_resize), POOL=7, C=256, N=1000.
// R12: R10 structure (single mixed-level param array, one prep launch, CPT=4,
// regs=32 / 8 blocks/SM) with params compressed 36B -> 20B per sample:
//   int4 {o.x|dx|dy|level, outbase, a=m*(1-wy), b=m*wy} + float wx.
// Corner offsets and weights are reconstructed bit-exactly in k2.

#define NBOX  1000
#define POOLP 49
#define CCH   256
#define MAXS  (NBOX * POOLP)     // 49000
#define CPT   4                  // channels per thread in hot kernel
#define NCG   (CCH / CPT)        // 64 channel groups
#define CHUNKS 16                // k2 grid.y; stride = 256*CHUNKS = 4096

__device__ int4  g_pk[MAXS];     // {w0, ob, bits(a), bits(b)}
__device__ float g_wx[MAXS];     // wx

// -- one-shot prep: per-sample level + packed bilinear params --------------
__global__ __launch_bounds__(256) void kP(const float* __restrict__ boxes) {
    const int s = blockIdx.x * blockDim.x + threadIdx.x;
    if (s >= MAXS) return;

    const int n   = s / POOLP;
    const int pos = s - n * POOLP;
    const int py = pos / 7;
    const int px = pos - py * 7;

    const float y1 = __ldg(boxes + n * 4 + 0);
    const float x1 = __ldg(boxes + n * 4 + 1);
    const float y2 = __ldg(boxes + n * 4 + 2);
    const float x2 = __ldg(boxes + n * 4 + 3);

    // roi_level = clip(round(4 + log2(sqrt(h*w)/0.21875)), 2, 5); round half-to-even.
    const float lvl_f = 4.0f + log2f(sqrtf((y2 - y1) * (x2 - x1)) / 0.21875f);
    int lvl = (int)rintf(lvl_f);
    lvl = lvl < 2 ? 2 : (lvl > 5 ? 5 : lvl);
    const int l = lvl - 2;

    const int H = 256 >> l;
    const int W = H;

    // Match jax f32 arithmetic (t = i / 6.0f as division).
    const float ty = (float)py / 6.0f;
    const float tx = (float)px / 6.0f;
    const float yy = (y1 + (y2 - y1) * ty) * (float)(H - 1);
    const float xx = (x1 + (x2 - x1) * tx) * (float)(W - 1);

    const float y0f = floorf(yy);
    const float x0f = floorf(xx);
    const float wy = yy - y0f;
    const float wx = xx - x0f;

    int iy0 = (int)y0f; iy0 = iy0 < 0 ? 0 : (iy0 > H - 1 ? H - 1 : iy0);
    int iy1 = (iy0 + 1 > H - 1) ? (H - 1) : (iy0 + 1);
    int ix0 = (int)x0f; ix0 = ix0 < 0 ? 0 : (ix0 > W - 1 ? W - 1 : ix0);
    int ix1 = (ix0 + 1 > W - 1) ? (W - 1) : (ix0 + 1);

    const bool inb = (yy >= 0.0f) && (yy <= (float)(H - 1)) &&
                     (xx >= 0.0f) && (xx <= (float)(W - 1));
    const float m = inb ? 1.0f : 0.0f;

    const int ox = iy0 * W + ix0;          // <= 65535
    const int dx = ix1 - ix0;              // 0/1
    const int dy = iy1 - iy0;              // 0/1
    const int w0 = ox | (dx << 16) | (dy << 17) | (l << 18);

    const float a = m * (1.0f - wy);       // (m*(1-wy)) — matches original assoc
    const float b = m * wy;                // (m*wy)

    int4 pk;
    pk.x = w0;
    pk.y = n * (CCH * POOLP) + pos;
    pk.z = __float_as_int(a);
    pk.w = __float_as_int(b);
    g_pk[s] = pk;
    g_wx[s] = wx;
}

// -- hot kernel: (channel-group of 4, chunk); mixed levels per block -------
__global__ __launch_bounds__(256) void k2(
    const float* __restrict__ p2,
    const float* __restrict__ p3,
    const float* __restrict__ p4,
    const float* __restrict__ p5,
    float* __restrict__ out)
{
    const int cg    = blockIdx.x;   // 0..NCG-1
    const int chunk = blockIdx.y;   // 0..CHUNKS-1
    const int c0 = cg * CPT;

    const int j0 = chunk * 256 + threadIdx.x;

    for (int j = j0; j < MAXS; j += 256 * CHUNKS) {
        const int4  pk = __ldg(g_pk + j);
        const float wx = __ldg(g_wx + j);

        const int w0 = pk.x;
        const int ob = pk.y;
        const float a = __int_as_float(pk.z);
        const float b = __int_as_float(pk.w);

        const int ox = w0 & 0xFFFF;
        const int dx = (w0 >> 16) & 1;
        const int l  = (w0 >> 18) & 3;
        const int W  = 256 >> l;
        const int HW = W * W;
        const int oz = ox + ((w0 >> 17) & 1 ? W : 0);

        const int o_x = ox;
        const int o_y = ox + dx;
        const int o_z = oz;
        const int o_w = oz + dx;

        const float cx = 1.0f - wx;
        const float w00 = a * cx;
        const float w01 = a * wx;
        const float w10 = b * cx;
        const float w11 = b * wx;

        const float* fm = (l == 0) ? p2 : (l == 1) ? p3 : (l == 2) ? p4 : p5;
        const float* __restrict__ base = fm + (size_t)c0 * HW;

        float v[CPT];
        #pragma unroll
        for (int k = 0; k < CPT; ++k) {
            const float* __restrict__ pl = base + (size_t)k * HW;
            v[k] = w00 * __ldg(pl + o_x) + w01 * __ldg(pl + o_y)
                 + w10 * __ldg(pl + o_z) + w11 * __ldg(pl + o_w);
        }
        #pragma unroll
        for (int k = 0; k < CPT; ++k)
            out[ob + (c0 + k) * POOLP] = v[k];
    }
}

extern "C" void kernel_launch(void* const* d_in, const int* in_sizes, int n_in,
                              void* d_out, int out_size)
{
    const float* boxes = (const float*)d_in[0];
    const float* p2    = (const float*)d_in[1];
    const float* p3    = (const float*)d_in[2];
    const float* p4    = (const float*)d_in[3];
    const float* p5    = (const float*)d_in[4];
    float* out = (float*)d_out;

    kP<<<(MAXS + 255) / 256, 256>>>(boxes);
    k2<<<dim3(NCG, CHUNKS), 256>>>(p2, p3, p4, p5, out);
}